// round 12
// baseline (speedup 1.0000x reference)
#include <cuda_runtime.h>
#include <math.h>

#define B_ 1024
#define S_ 512
#define D_ 768
#define FEAT 2304      // 3*D
#define H1 256
#define H2 64
#define NC 4

#define CCH 6          // union-chunks per batch in span phase

#define TM1 32         // batches per stage1 block
#define NPAIR (TM1/2)  // 16 packed f32 pairs
#define SFSTRIDE (NPAIR + 2)   // padded smem row stride (u64s), keeps 16B align
#define KSPLIT 9
#define KCHUNK 256     // FEAT / KSPLIT  (divides 768 -> chunk regions are pure)
#define KT 32          // W1 k-tile staged in smem

#define NCLS 96        // cls stage1 blocks fused into the span launch (3 chunks x 32)
#define TMF 2          // batches per finish block

// Scratch (static device globals; no allocation allowed)
__device__ float g_part[2 * CCH * B_ * D_];     // [e][c][b][f] raw span sums
__device__ float g_h1p[KSPLIT * B_ * H1];       // [chunk][b][j] stage1 partials

// ---------------------------------------------------------------------------
// packed fp32x2 helpers (FFMA2 path — PTX-only on sm_103a)
// ---------------------------------------------------------------------------
__device__ __forceinline__ unsigned long long pack2(float lo, float hi) {
    unsigned long long u;
    asm("mov.b64 %0, {%1, %2};" : "=l"(u) : "f"(lo), "f"(hi));
    return u;
}
__device__ __forceinline__ void unpack2(unsigned long long u, float& lo, float& hi) {
    asm("mov.b64 {%0, %1}, %2;" : "=f"(lo), "=f"(hi) : "l"(u));
}
__device__ __forceinline__ void ffma2(unsigned long long& d, unsigned long long a,
                                      unsigned long long b, unsigned long long c) {
    asm("fma.rn.f32x2 %0, %1, %2, %3;" : "=l"(d) : "l"(a), "l"(b), "l"(c));
}

// ---------------------------------------------------------------------------
// stage1 body (single-buffered, proven): computes h1p[chunk][b0..b0+31][0..255]
// over K-chunk `chunk`. Feat built on the fly: chunks 0-2 e1-mean, 3-5 e2-mean,
// 6-8 cls. 256 threads. Called from both the fused kernel and stage1_kernel.
// ---------------------------------------------------------------------------
__device__ __forceinline__ void stage1_body(
    const float* __restrict__ part,
    const float* __restrict__ x,
    const int*   __restrict__ e1_span,
    const int*   __restrict__ e2_span,
    const float* __restrict__ W1,
    float*       __restrict__ h1p,
    int b0, int chunk,
    unsigned long long* sfP, float* sW)
{
    const int j = threadIdx.x;

    // staging: thread = (pair p = j>>4, kgroup kg = j&15); coalesced float4s.
    {
        const int kg = j & 15;
        const int p  = j >> 4;
        const int bA = b0 + 2 * p;
        const int bB = bA + 1;

        if (chunk >= 6) {
            // cls region: read x[b][0][k0+k]
            const int k0 = chunk * KCHUNK - 1536;
            const float* rA = x + (size_t)bA * S_ * D_ + k0;
            const float* rB = x + (size_t)bB * S_ * D_ + k0;
            #pragma unroll
            for (int kb = 0; kb < KCHUNK / 64; kb++) {
                const int k = kb * 64 + kg * 4;
                const float4 v0 = *(const float4*)(rA + k);
                const float4 v1 = *(const float4*)(rB + k);
                sfP[(k + 0) * SFSTRIDE + p] = pack2(v0.x, v1.x);
                sfP[(k + 1) * SFSTRIDE + p] = pack2(v0.y, v1.y);
                sfP[(k + 2) * SFSTRIDE + p] = pack2(v0.z, v1.z);
                sfP[(k + 3) * SFSTRIDE + p] = pack2(v0.w, v1.w);
            }
        } else {
            const int e  = (chunk < 3) ? 0 : 1;
            const int k0 = chunk * KCHUNK - e * 768;
            const int* sp = e ? e2_span : e1_span;
            int loA = sp[2 * bA], hiA = sp[2 * bA + 1];
            if (hiA < loA + 1) hiA = loA + 1;
            int loB = sp[2 * bB], hiB = sp[2 * bB + 1];
            if (hiB < loB + 1) hiB = loB + 1;
            const float invA = 1.0f / (float)(hiA - loA);
            const float invB = 1.0f / (float)(hiB - loB);

            const float* pA = part + ((size_t)(e * CCH) * B_ + bA) * D_ + k0;
            const float* pB = part + ((size_t)(e * CCH) * B_ + bB) * D_ + k0;
            const size_t cs = (size_t)B_ * D_;

            #pragma unroll
            for (int kb = 0; kb < KCHUNK / 64; kb++) {
                const int k = kb * 64 + kg * 4;
                float4 sA = make_float4(0.f, 0.f, 0.f, 0.f);
                float4 sB = make_float4(0.f, 0.f, 0.f, 0.f);
                #pragma unroll
                for (int cc = 0; cc < CCH; cc++) {
                    const float4 vA = *(const float4*)(pA + cc * cs + k);
                    const float4 vB = *(const float4*)(pB + cc * cs + k);
                    sA.x += vA.x; sA.y += vA.y; sA.z += vA.z; sA.w += vA.w;
                    sB.x += vB.x; sB.y += vB.y; sB.z += vB.z; sB.w += vB.w;
                }
                sfP[(k + 0) * SFSTRIDE + p] = pack2(sA.x * invA, sB.x * invB);
                sfP[(k + 1) * SFSTRIDE + p] = pack2(sA.y * invA, sB.y * invB);
                sfP[(k + 2) * SFSTRIDE + p] = pack2(sA.z * invA, sB.z * invB);
                sfP[(k + 3) * SFSTRIDE + p] = pack2(sA.w * invA, sB.w * invB);
            }
        }
    }

    const int jh = j & 127;          // column pair: jh, jh+128
    const int mg = j >> 7;           // batch-pair group: 8*mg .. 8*mg+7
    const int pb = 8 * mg;

    unsigned long long acc0[8], acc1[8];
    #pragma unroll
    for (int q = 0; q < 8; q++) { acc0[q] = 0ULL; acc1[q] = 0ULL; }

    const float* W1c = W1 + (size_t)chunk * KCHUNK * H1;

    __syncthreads();

    for (int kt = 0; kt < KCHUNK; kt += KT) {
        {
            const float4* src = (const float4*)(W1c + (size_t)kt * H1);
            float4*       dst = (float4*)sW;
            #pragma unroll
            for (int i = 0; i < (KT * H1 / 4) / 256; i++)
                dst[j + i * 256] = src[j + i * 256];
        }
        __syncthreads();

        #pragma unroll
        for (int kk = 0; kk < KT; kk++) {
            const float w0 = sW[kk * H1 + jh];
            const float w1 = sW[kk * H1 + jh + 128];
            const unsigned long long wp0 = pack2(w0, w0);
            const unsigned long long wp1 = pack2(w1, w1);
            const ulonglong2* fr = (const ulonglong2*)&sfP[(kt + kk) * SFSTRIDE + pb];
            #pragma unroll
            for (int q2 = 0; q2 < 4; q2++) {
                ulonglong2 f = fr[q2];          // broadcast LDS.128 (2 pairs)
                ffma2(acc0[2 * q2 + 0], f.x, wp0, acc0[2 * q2 + 0]);
                ffma2(acc0[2 * q2 + 1], f.y, wp0, acc0[2 * q2 + 1]);
                ffma2(acc1[2 * q2 + 0], f.x, wp1, acc1[2 * q2 + 0]);
                ffma2(acc1[2 * q2 + 1], f.y, wp1, acc1[2 * q2 + 1]);
            }
        }
        __syncthreads();
    }

    float* dst = h1p + ((size_t)chunk * B_ + b0) * H1;
    #pragma unroll
    for (int q = 0; q < 8; q++) {
        const int p = pb + q;
        float lo, hi;
        unpack2(acc0[q], lo, hi);
        dst[(2 * p + 0) * H1 + jh] = lo;
        dst[(2 * p + 1) * H1 + jh] = hi;
        unpack2(acc1[q], lo, hi);
        dst[(2 * p + 0) * H1 + jh + 128] = lo;
        dst[(2 * p + 1) * H1 + jh + 128] = hi;
    }
}

// ---------------------------------------------------------------------------
// span body: partial sums over 1/CCH of the CONCATENATED UNION of spans.
// 192 active threads; thread t owns float4 (cols 4t..4t+3). No barriers.
// ---------------------------------------------------------------------------
__device__ __forceinline__ void span_body(
    const float* __restrict__ x,
    const int*   __restrict__ e1_span,
    const int*   __restrict__ e2_span,
    float*       __restrict__ part,
    int b, int c, int t)
{
    int lo1 = e1_span[2 * b], hi1 = e1_span[2 * b + 1];
    if (hi1 < lo1 + 1) hi1 = lo1 + 1;
    int lo2 = e2_span[2 * b], hi2 = e2_span[2 * b + 1];
    if (hi2 < lo2 + 1) hi2 = lo2 + 1;

    const int u_lo = min(lo1, lo2);
    const int u_hi = max(hi1, hi2);
    int g_lo = min(hi1, hi2);
    int g_hi = max(lo1, lo2);
    if (g_hi < g_lo) { g_lo = u_hi; g_hi = u_hi; }   // overlap: no gap

    const int L1 = g_lo - u_lo;
    const int L2 = u_hi - g_hi;
    const int L  = L1 + L2;

    const int r0 = (c * L) / CCH;
    const int r1 = ((c + 1) * L) / CCH;

    const int s1a = u_lo + min(r0, L1);
    const int s1b = u_lo + min(r1, L1);
    const int s2a = g_hi + max(r0 - L1, 0);
    const int s2b = g_hi + max(r1 - L1, 0);

    const float4* xb = (const float4*)(x + (size_t)b * S_ * D_);

    float4 a1 = make_float4(0.f, 0.f, 0.f, 0.f);
    float4 a2 = make_float4(0.f, 0.f, 0.f, 0.f);

    #pragma unroll 1
    for (int seg = 0; seg < 2; seg++) {
        const int s0 = (seg == 0) ? s1a : s2a;
        const int s1 = (seg == 0) ? s1b : s2b;
        int s = s0;
        for (; s + 4 <= s1; s += 4) {
            float4 q0 = __ldcs(&xb[(size_t)(s + 0) * 192 + t]);
            float4 q1 = __ldcs(&xb[(size_t)(s + 1) * 192 + t]);
            float4 q2 = __ldcs(&xb[(size_t)(s + 2) * 192 + t]);
            float4 q3 = __ldcs(&xb[(size_t)(s + 3) * 192 + t]);
            #pragma unroll
            for (int u = 0; u < 4; u++) {
                const int ss = s + u;
                const float4 r = (u == 0) ? q0 : (u == 1) ? q1 : (u == 2) ? q2 : q3;
                const float p1 = (ss >= lo1 && ss < hi1) ? 1.0f : 0.0f;
                const float p2 = (ss >= lo2 && ss < hi2) ? 1.0f : 0.0f;
                a1.x = fmaf(r.x, p1, a1.x); a1.y = fmaf(r.y, p1, a1.y);
                a1.z = fmaf(r.z, p1, a1.z); a1.w = fmaf(r.w, p1, a1.w);
                a2.x = fmaf(r.x, p2, a2.x); a2.y = fmaf(r.y, p2, a2.y);
                a2.z = fmaf(r.z, p2, a2.z); a2.w = fmaf(r.w, p2, a2.w);
            }
        }
        for (; s < s1; s++) {
            float4 r = __ldcs(&xb[(size_t)s * 192 + t]);
            const float p1 = (s >= lo1 && s < hi1) ? 1.0f : 0.0f;
            const float p2 = (s >= lo2 && s < hi2) ? 1.0f : 0.0f;
            a1.x = fmaf(r.x, p1, a1.x); a1.y = fmaf(r.y, p1, a1.y);
            a1.z = fmaf(r.z, p1, a1.z); a1.w = fmaf(r.w, p1, a1.w);
            a2.x = fmaf(r.x, p2, a2.x); a2.y = fmaf(r.y, p2, a2.y);
            a2.z = fmaf(r.z, p2, a2.z); a2.w = fmaf(r.w, p2, a2.w);
        }
    }

    float4* p1 = (float4*)(part + ((size_t)(0 * CCH + c) * B_ + b) * D_);
    float4* p2 = (float4*)(part + ((size_t)(1 * CCH + c) * B_ + b) * D_);
    __stcs(&p1[t], a1);
    __stcs(&p2[t], a2);
}

// ---------------------------------------------------------------------------
// Kernel 1 (FUSED): first NCLS blocks run cls-stage1 (chunks 6-8, independent
// of span output, dispatched in wave 1 so they hide under the DRAM-bound span);
// remaining 6144 blocks run span partial sums.
// 256 threads, 69632B dynamic smem.
// ---------------------------------------------------------------------------
__global__ __launch_bounds__(256) void fused_span_cls_kernel(
    const float* __restrict__ x,
    const int*   __restrict__ e1_span,
    const int*   __restrict__ e2_span,
    float*       __restrict__ part,
    const float* __restrict__ W1,
    float*       __restrict__ h1p)
{
    extern __shared__ unsigned long long smem_dyn[];

    if (blockIdx.x < NCLS) {
        const int idx   = blockIdx.x;
        const int b0    = (idx & 31) * TM1;
        const int chunk = 6 + (idx >> 5);
        unsigned long long* sfP = smem_dyn;
        float* sW = (float*)(smem_dyn + KCHUNK * SFSTRIDE);
        stage1_body(part, x, e1_span, e2_span, W1, h1p, b0, chunk, sfP, sW);
    } else {
        const int t = threadIdx.x;
        if (t >= 192) return;                 // span uses 192 threads, no barriers
        const int idx = blockIdx.x - NCLS;    // 0..6143
        const int b = idx / CCH;
        const int c = idx - b * CCH;
        span_body(x, e1_span, e2_span, part, b, c, t);
    }
}

// ---------------------------------------------------------------------------
// Kernel 2: stage-1 GEMM partials for chunks 0-5 (span-dependent part).
// grid = (B/TM1, 6), 256 threads.
// ---------------------------------------------------------------------------
__global__ __launch_bounds__(256) void stage1_kernel(
    const float* __restrict__ part,
    const float* __restrict__ x,
    const int*   __restrict__ e1_span,
    const int*   __restrict__ e2_span,
    const float* __restrict__ W1,
    float*       __restrict__ h1p)
{
    extern __shared__ unsigned long long smem_dyn[];
    unsigned long long* sfP = smem_dyn;
    float* sW = (float*)(smem_dyn + KCHUNK * SFSTRIDE);
    stage1_body(part, x, e1_span, e2_span, W1, h1p,
                blockIdx.x * TM1, blockIdx.y, sfP, sW);
}

// ---------------------------------------------------------------------------
// Kernel 3: finish. 256 threads, grid B/TMF (=512 blocks for latency hiding).
// W2 fully staged in dynamic smem, staged first to overlap the h1p loads.
// ---------------------------------------------------------------------------
__global__ __launch_bounds__(256) void finish_kernel(
    const float* __restrict__ h1p,
    const float* __restrict__ b1,
    const float* __restrict__ W2, const float* __restrict__ b2,
    const float* __restrict__ W3, const float* __restrict__ b3,
    float*       __restrict__ out)
{
    extern __shared__ float fsm[];
    float* sW2 = fsm;                    // H1*H2 = 64 KB
    float* sh1 = sW2 + H1 * H2;          // TMF*H1
    float* sh2 = sh1 + TMF * H1;         // TMF*H2

    const int j  = threadIdx.x;
    const int b0 = blockIdx.x * TMF;

    // stage ALL of W2 (issued first so these loads overlap the h1p loads)
    {
        const float4* src = (const float4*)W2;
        float4*       dst = (float4*)sW2;
        #pragma unroll
        for (int i = 0; i < (H1 * H2 / 4) / 256; i++)
            dst[j + i * 256] = src[j + i * 256];
    }

    // sum split-K partials + bias + relu
    {
        const float bias = b1[j];
        #pragma unroll
        for (int m = 0; m < TMF; m++) {
            const size_t off = (size_t)(b0 + m) * H1 + j;
            float v = bias;
            #pragma unroll
            for (int c = 0; c < KSPLIT; c++)
                v += h1p[(size_t)c * B_ * H1 + off];
            sh1[m * H1 + j] = fmaxf(v, 0.f);
        }
    }
    __syncthreads();

    // stage 2: threads 0..TMF*H2-1: one (batch m, column j2) per thread
    if (j < TMF * H2) {
        const int m  = j >> 6;
        const int j2 = j & 63;
        float a = b2[j2];
        #pragma unroll 16
        for (int k = 0; k < H1; k++)
            a = fmaf(sh1[m * H1 + k], sW2[k * H2 + j2], a);
        sh2[m * H2 + j2] = fmaxf(a, 0.f);
    }
    __syncthreads();

    // stage 3 + softmax: one thread per batch
    if (j < TMF) {
        const int mm = j;
        float l0 = b3[0], l1 = b3[1], l2 = b3[2], l3 = b3[3];
        #pragma unroll 8
        for (int k = 0; k < H2; k++) {
            const float h = sh2[mm * H2 + k];
            l0 = fmaf(h, W3[k * NC + 0], l0);
            l1 = fmaf(h, W3[k * NC + 1], l1);
            l2 = fmaf(h, W3[k * NC + 2], l2);
            l3 = fmaf(h, W3[k * NC + 3], l3);
        }
        const float mx = fmaxf(fmaxf(l0, l1), fmaxf(l2, l3));
        const float e0 = __expf(l0 - mx), e1v = __expf(l1 - mx);
        const float e2v = __expf(l2 - mx), e3v = __expf(l3 - mx);
        const float inv = 1.0f / (e0 + e1v + e2v + e3v);
        float* o = out + (size_t)(b0 + mm) * NC;
        o[0] = e0 * inv; o[1] = e1v * inv; o[2] = e2v * inv; o[3] = e3v * inv;
    }
}

// ---------------------------------------------------------------------------
extern "C" void kernel_launch(void* const* d_in, const int* in_sizes, int n_in,
                              void* d_out, int out_size)
{
    const float* x       = (const float*)d_in[0];
    const int*   e1_span = (const int*)  d_in[1];
    const int*   e2_span = (const int*)  d_in[2];
    const float* W1      = (const float*)d_in[3];
    const float* b1      = (const float*)d_in[4];
    const float* W2      = (const float*)d_in[5];
    const float* b2      = (const float*)d_in[6];
    const float* W3      = (const float*)d_in[7];
    const float* b3      = (const float*)d_in[8];
    float* out = (float*)d_out;

    float *part, *h1p;
    cudaGetSymbolAddress((void**)&part, g_part);
    cudaGetSymbolAddress((void**)&h1p,  g_h1p);

    const int stage1_smem = KCHUNK * SFSTRIDE * 8 + KT * H1 * 4;        // 69632
    const int finish_smem = (H1 * H2 + TMF * H1 + TMF * H2) * 4;        // ~68 KB
    cudaFuncSetAttribute(fused_span_cls_kernel,
                         cudaFuncAttributeMaxDynamicSharedMemorySize, stage1_smem);
    cudaFuncSetAttribute(stage1_kernel,
                         cudaFuncAttributeMaxDynamicSharedMemorySize, stage1_smem);
    cudaFuncSetAttribute(finish_kernel,
                         cudaFuncAttributeMaxDynamicSharedMemorySize, finish_smem);

    fused_span_cls_kernel<<<NCLS + B_ * CCH, 256, stage1_smem>>>(
        x, e1_span, e2_span, part, W1, h1p);
    stage1_kernel<<<dim3(B_ / TM1, 6), 256, stage1_smem>>>(
        part, x, e1_span, e2_span, W1, h1p);
    finish_kernel<<<B_ / TMF, 256, finish_smem>>>(h1p, b1, W2, b2, W3, b3, out);
}

// round 14
// speedup vs baseline: 1.1651x; 1.1651x over previous
#include <cuda_runtime.h>
#include <math.h>

#define B_ 1024
#define S_ 512
#define D_ 768
#define FEAT 2304      // 3*D
#define H1 256
#define H2 64
#define NC 4

#define CCH 6          // union-chunks per batch in span phase

#define TM1 32         // batches per stage1 block
#define NPAIR (TM1/2)  // 16 packed f32 pairs
#define SFSTRIDE (NPAIR + 2)   // padded smem row stride (u64s), keeps 16B align
#define KSPLIT 9
#define KCHUNK 256     // FEAT / KSPLIT  (divides 768 -> chunk regions are pure)
#define KT 32          // W1 k-tile staged in smem

#define TMF 2          // batches per finish block

// Scratch (static device globals; no allocation allowed)
__device__ float g_part[2 * CCH * B_ * D_];     // [e][c][b][f] raw span sums
__device__ float g_h1p[KSPLIT * B_ * H1];       // [chunk][b][j] stage1 partials

// ---------------------------------------------------------------------------
// packed fp32x2 helpers (FFMA2 path — PTX-only on sm_103a)
// ---------------------------------------------------------------------------
__device__ __forceinline__ unsigned long long pack2(float lo, float hi) {
    unsigned long long u;
    asm("mov.b64 %0, {%1, %2};" : "=l"(u) : "f"(lo), "f"(hi));
    return u;
}
__device__ __forceinline__ void unpack2(unsigned long long u, float& lo, float& hi) {
    asm("mov.b64 {%0, %1}, %2;" : "=f"(lo), "=f"(hi) : "l"(u));
}
__device__ __forceinline__ void ffma2(unsigned long long& d, unsigned long long a,
                                      unsigned long long b, unsigned long long c) {
    asm("fma.rn.f32x2 %0, %1, %2, %3;" : "=l"(d) : "l"(a), "l"(b), "l"(c));
}

// ---------------------------------------------------------------------------
// Kernel 1: span partial sums over 1/CCH of the CONCATENATED UNION of spans.
// grid = (B, CCH), 192 threads; thread t owns float4 (cols 4t..4t+3).
// Streaming loads/stores: x and part have zero reuse.  (R11-proven, smem 0.)
// ---------------------------------------------------------------------------
__global__ __launch_bounds__(192) void span_chunk_kernel(
    const float* __restrict__ x,
    const int*   __restrict__ e1_span,
    const int*   __restrict__ e2_span,
    float*       __restrict__ part)
{
    const int b = blockIdx.x;
    const int c = blockIdx.y;
    const int t = threadIdx.x;

    int lo1 = e1_span[2 * b], hi1 = e1_span[2 * b + 1];
    if (hi1 < lo1 + 1) hi1 = lo1 + 1;
    int lo2 = e2_span[2 * b], hi2 = e2_span[2 * b + 1];
    if (hi2 < lo2 + 1) hi2 = lo2 + 1;

    const int u_lo = min(lo1, lo2);
    const int u_hi = max(hi1, hi2);
    int g_lo = min(hi1, hi2);
    int g_hi = max(lo1, lo2);
    if (g_hi < g_lo) { g_lo = u_hi; g_hi = u_hi; }   // overlap: no gap

    const int L1 = g_lo - u_lo;          // segment 1 length
    const int L2 = u_hi - g_hi;          // segment 2 length
    const int L  = L1 + L2;

    const int r0 = (c * L) / CCH;        // my slice of the concatenated union
    const int r1 = ((c + 1) * L) / CCH;

    const int s1a = u_lo + min(r0, L1);
    const int s1b = u_lo + min(r1, L1);
    const int s2a = g_hi + max(r0 - L1, 0);
    const int s2b = g_hi + max(r1 - L1, 0);

    const float4* xb = (const float4*)(x + (size_t)b * S_ * D_);

    float4 a1 = make_float4(0.f, 0.f, 0.f, 0.f);
    float4 a2 = make_float4(0.f, 0.f, 0.f, 0.f);

    #pragma unroll 1
    for (int seg = 0; seg < 2; seg++) {
        const int s0 = (seg == 0) ? s1a : s2a;
        const int s1 = (seg == 0) ? s1b : s2b;
        int s = s0;
        for (; s + 4 <= s1; s += 4) {
            float4 q0 = __ldcs(&xb[(size_t)(s + 0) * 192 + t]);
            float4 q1 = __ldcs(&xb[(size_t)(s + 1) * 192 + t]);
            float4 q2 = __ldcs(&xb[(size_t)(s + 2) * 192 + t]);
            float4 q3 = __ldcs(&xb[(size_t)(s + 3) * 192 + t]);
            #pragma unroll
            for (int u = 0; u < 4; u++) {
                const int ss = s + u;
                const float4 r = (u == 0) ? q0 : (u == 1) ? q1 : (u == 2) ? q2 : q3;
                const float p1 = (ss >= lo1 && ss < hi1) ? 1.0f : 0.0f;
                const float p2 = (ss >= lo2 && ss < hi2) ? 1.0f : 0.0f;
                a1.x = fmaf(r.x, p1, a1.x); a1.y = fmaf(r.y, p1, a1.y);
                a1.z = fmaf(r.z, p1, a1.z); a1.w = fmaf(r.w, p1, a1.w);
                a2.x = fmaf(r.x, p2, a2.x); a2.y = fmaf(r.y, p2, a2.y);
                a2.z = fmaf(r.z, p2, a2.z); a2.w = fmaf(r.w, p2, a2.w);
            }
        }
        for (; s < s1; s++) {
            float4 r = __ldcs(&xb[(size_t)s * 192 + t]);
            const float p1 = (s >= lo1 && s < hi1) ? 1.0f : 0.0f;
            const float p2 = (s >= lo2 && s < hi2) ? 1.0f : 0.0f;
            a1.x = fmaf(r.x, p1, a1.x); a1.y = fmaf(r.y, p1, a1.y);
            a1.z = fmaf(r.z, p1, a1.z); a1.w = fmaf(r.w, p1, a1.w);
            a2.x = fmaf(r.x, p2, a2.x); a2.y = fmaf(r.y, p2, a2.y);
            a2.z = fmaf(r.z, p2, a2.z); a2.w = fmaf(r.w, p2, a2.w);
        }
    }

    float4* p1 = (float4*)(part + ((size_t)(0 * CCH + c) * B_ + b) * D_);
    float4* p2 = (float4*)(part + ((size_t)(1 * CCH + c) * B_ + b) * D_);
    __stcs(&p1[t], a1);
    __stcs(&p2[t], a2);
}

// ---------------------------------------------------------------------------
// Kernel 2: stage-1 GEMM partials with packed f32x2 FMA + W-tile register
// prefetch pipeline (LDG of tile kt+1 overlaps compute of tile kt).
// grid = (B/TM1, KSPLIT) = 288 blocks, 256 threads.
// Register tile: thread (jh = tid&127, mg = tid>>7) owns columns {jh, jh+128}
// and batch-pairs [8*mg, 8*mg+8).
// ---------------------------------------------------------------------------
__global__ __launch_bounds__(256) void stage1_kernel(
    const float* __restrict__ part,
    const float* __restrict__ x,
    const int*   __restrict__ e1_span,
    const int*   __restrict__ e2_span,
    const float* __restrict__ W1,
    float*       __restrict__ h1p)
{
    extern __shared__ unsigned long long smem_dyn[];
    unsigned long long* sfP = smem_dyn;                        // KCHUNK*SFSTRIDE
    float* sW = (float*)(smem_dyn + KCHUNK * SFSTRIDE);        // KT*H1 floats

    const int j     = threadIdx.x;
    const int b0    = blockIdx.x * TM1;
    const int chunk = blockIdx.y;

    // staging: thread = (pair p = j>>4, kgroup kg = j&15); coalesced float4s.
    {
        const int kg = j & 15;
        const int p  = j >> 4;
        const int bA = b0 + 2 * p;
        const int bB = bA + 1;

        if (chunk >= 6) {
            // cls region: read x[b][0][k0+k]
            const int k0 = chunk * KCHUNK - 1536;
            const float* rA = x + (size_t)bA * S_ * D_ + k0;
            const float* rB = x + (size_t)bB * S_ * D_ + k0;
            #pragma unroll
            for (int kb = 0; kb < KCHUNK / 64; kb++) {
                const int k = kb * 64 + kg * 4;
                const float4 v0 = *(const float4*)(rA + k);
                const float4 v1 = *(const float4*)(rB + k);
                sfP[(k + 0) * SFSTRIDE + p] = pack2(v0.x, v1.x);
                sfP[(k + 1) * SFSTRIDE + p] = pack2(v0.y, v1.y);
                sfP[(k + 2) * SFSTRIDE + p] = pack2(v0.z, v1.z);
                sfP[(k + 3) * SFSTRIDE + p] = pack2(v0.w, v1.w);
            }
        } else {
            const int e  = (chunk < 3) ? 0 : 1;
            const int k0 = chunk * KCHUNK - e * 768;
            const int* sp = e ? e2_span : e1_span;
            int loA = sp[2 * bA], hiA = sp[2 * bA + 1];
            if (hiA < loA + 1) hiA = loA + 1;
            int loB = sp[2 * bB], hiB = sp[2 * bB + 1];
            if (hiB < loB + 1) hiB = loB + 1;
            const float invA = 1.0f / (float)(hiA - loA);
            const float invB = 1.0f / (float)(hiB - loB);

            const float* pA = part + ((size_t)(e * CCH) * B_ + bA) * D_ + k0;
            const float* pB = part + ((size_t)(e * CCH) * B_ + bB) * D_ + k0;
            const size_t cs = (size_t)B_ * D_;

            #pragma unroll
            for (int kb = 0; kb < KCHUNK / 64; kb++) {
                const int k = kb * 64 + kg * 4;
                float4 sA = make_float4(0.f, 0.f, 0.f, 0.f);
                float4 sB = make_float4(0.f, 0.f, 0.f, 0.f);
                #pragma unroll
                for (int cc = 0; cc < CCH; cc++) {
                    const float4 vA = *(const float4*)(pA + cc * cs + k);
                    const float4 vB = *(const float4*)(pB + cc * cs + k);
                    sA.x += vA.x; sA.y += vA.y; sA.z += vA.z; sA.w += vA.w;
                    sB.x += vB.x; sB.y += vB.y; sB.z += vB.z; sB.w += vB.w;
                }
                sfP[(k + 0) * SFSTRIDE + p] = pack2(sA.x * invA, sB.x * invB);
                sfP[(k + 1) * SFSTRIDE + p] = pack2(sA.y * invA, sB.y * invB);
                sfP[(k + 2) * SFSTRIDE + p] = pack2(sA.z * invA, sB.z * invB);
                sfP[(k + 3) * SFSTRIDE + p] = pack2(sA.w * invA, sB.w * invB);
            }
        }
    }

    const int jh = j & 127;          // column pair: jh, jh+128
    const int mg = j >> 7;           // batch-pair group: 8*mg .. 8*mg+7
    const int pb = 8 * mg;

    unsigned long long acc0[8], acc1[8];
    #pragma unroll
    for (int q = 0; q < 8; q++) { acc0[q] = 0ULL; acc1[q] = 0ULL; }

    const float* W1c = W1 + (size_t)chunk * KCHUNK * H1;

    // prefetch first W tile into registers (overlaps the staging stores above)
    float4 wreg[(KT * H1 / 4) / 256];               // 8 x float4
    {
        const float4* src = (const float4*)W1c;
        #pragma unroll
        for (int i = 0; i < (KT * H1 / 4) / 256; i++)
            wreg[i] = src[j + i * 256];
    }

    __syncthreads();   // sfP ready

    for (int kt = 0; kt < KCHUNK; kt += KT) {
        // commit prefetched tile to smem
        {
            float4* dst = (float4*)sW;
            #pragma unroll
            for (int i = 0; i < (KT * H1 / 4) / 256; i++)
                dst[j + i * 256] = wreg[i];
        }
        // prefetch NEXT tile (LDG latency hides under this tile's compute)
        if (kt + KT < KCHUNK) {
            const float4* src = (const float4*)(W1c + (size_t)(kt + KT) * H1);
            #pragma unroll
            for (int i = 0; i < (KT * H1 / 4) / 256; i++)
                wreg[i] = src[j + i * 256];
        }
        __syncthreads();   // sW ready

        #pragma unroll
        for (int kk = 0; kk < KT; kk++) {
            const float w0 = sW[kk * H1 + jh];
            const float w1 = sW[kk * H1 + jh + 128];
            const unsigned long long wp0 = pack2(w0, w0);
            const unsigned long long wp1 = pack2(w1, w1);
            const ulonglong2* fr = (const ulonglong2*)&sfP[(kt + kk) * SFSTRIDE + pb];
            #pragma unroll
            for (int q2 = 0; q2 < 4; q2++) {
                ulonglong2 f = fr[q2];          // broadcast LDS.128 (2 pairs)
                ffma2(acc0[2 * q2 + 0], f.x, wp0, acc0[2 * q2 + 0]);
                ffma2(acc0[2 * q2 + 1], f.y, wp0, acc0[2 * q2 + 1]);
                ffma2(acc1[2 * q2 + 0], f.x, wp1, acc1[2 * q2 + 0]);
                ffma2(acc1[2 * q2 + 1], f.y, wp1, acc1[2 * q2 + 1]);
            }
        }
        __syncthreads();   // compute done before next tile overwrites sW
    }

    float* dst = h1p + ((size_t)chunk * B_ + b0) * H1;
    #pragma unroll
    for (int q = 0; q < 8; q++) {
        const int p = pb + q;
        float lo, hi;
        unpack2(acc0[q], lo, hi);
        dst[(2 * p + 0) * H1 + jh] = lo;
        dst[(2 * p + 1) * H1 + jh] = hi;
        unpack2(acc1[q], lo, hi);
        dst[(2 * p + 0) * H1 + jh + 128] = lo;
        dst[(2 * p + 1) * H1 + jh + 128] = hi;
    }
}

// ---------------------------------------------------------------------------
// Kernel 3: finish. 256 threads, grid B/TMF (=512 blocks for latency hiding).
// W2 fully staged in dynamic smem, staged first to overlap the h1p loads.
// ---------------------------------------------------------------------------
__global__ __launch_bounds__(256) void finish_kernel(
    const float* __restrict__ h1p,
    const float* __restrict__ b1,
    const float* __restrict__ W2, const float* __restrict__ b2,
    const float* __restrict__ W3, const float* __restrict__ b3,
    float*       __restrict__ out)
{
    extern __shared__ float fsm[];
    float* sW2 = fsm;                    // H1*H2 = 64 KB
    float* sh1 = sW2 + H1 * H2;          // TMF*H1
    float* sh2 = sh1 + TMF * H1;         // TMF*H2

    const int j  = threadIdx.x;
    const int b0 = blockIdx.x * TMF;

    // stage ALL of W2 (issued first so these loads overlap the h1p loads)
    {
        const float4* src = (const float4*)W2;
        float4*       dst = (float4*)sW2;
        #pragma unroll
        for (int i = 0; i < (H1 * H2 / 4) / 256; i++)
            dst[j + i * 256] = src[j + i * 256];
    }

    // sum split-K partials + bias + relu
    {
        const float bias = b1[j];
        #pragma unroll
        for (int m = 0; m < TMF; m++) {
            const size_t off = (size_t)(b0 + m) * H1 + j;
            float v = bias;
            #pragma unroll
            for (int c = 0; c < KSPLIT; c++)
                v += h1p[(size_t)c * B_ * H1 + off];
            sh1[m * H1 + j] = fmaxf(v, 0.f);
        }
    }
    __syncthreads();

    // stage 2: threads 0..TMF*H2-1: one (batch m, column j2) per thread
    if (j < TMF * H2) {
        const int m  = j >> 6;
        const int j2 = j & 63;
        float a = b2[j2];
        #pragma unroll 16
        for (int k = 0; k < H1; k++)
            a = fmaf(sh1[m * H1 + k], sW2[k * H2 + j2], a);
        sh2[m * H2 + j2] = fmaxf(a, 0.f);
    }
    __syncthreads();

    // stage 3 + softmax: one thread per batch
    if (j < TMF) {
        const int mm = j;
        float l0 = b3[0], l1 = b3[1], l2 = b3[2], l3 = b3[3];
        #pragma unroll 8
        for (int k = 0; k < H2; k++) {
            const float h = sh2[mm * H2 + k];
            l0 = fmaf(h, W3[k * NC + 0], l0);
            l1 = fmaf(h, W3[k * NC + 1], l1);
            l2 = fmaf(h, W3[k * NC + 2], l2);
            l3 = fmaf(h, W3[k * NC + 3], l3);
        }
        const float mx = fmaxf(fmaxf(l0, l1), fmaxf(l2, l3));
        const float e0 = __expf(l0 - mx), e1v = __expf(l1 - mx);
        const float e2v = __expf(l2 - mx), e3v = __expf(l3 - mx);
        const float inv = 1.0f / (e0 + e1v + e2v + e3v);
        float* o = out + (size_t)(b0 + mm) * NC;
        o[0] = e0 * inv; o[1] = e1v * inv; o[2] = e2v * inv; o[3] = e3v * inv;
    }
}

// ---------------------------------------------------------------------------
extern "C" void kernel_launch(void* const* d_in, const int* in_sizes, int n_in,
                              void* d_out, int out_size)
{
    const float* x       = (const float*)d_in[0];
    const int*   e1_span = (const int*)  d_in[1];
    const int*   e2_span = (const int*)  d_in[2];
    const float* W1      = (const float*)d_in[3];
    const float* b1      = (const float*)d_in[4];
    const float* W2      = (const float*)d_in[5];
    const float* b2      = (const float*)d_in[6];
    const float* W3      = (const float*)d_in[7];
    const float* b3      = (const float*)d_in[8];
    float* out = (float*)d_out;

    float *part, *h1p;
    cudaGetSymbolAddress((void**)&part, g_part);
    cudaGetSymbolAddress((void**)&h1p,  g_h1p);

    const int stage1_smem = KCHUNK * SFSTRIDE * 8 + KT * H1 * 4;        // 69632
    const int finish_smem = (H1 * H2 + TMF * H1 + TMF * H2) * 4;        // ~68 KB
    cudaFuncSetAttribute(stage1_kernel,
                         cudaFuncAttributeMaxDynamicSharedMemorySize, stage1_smem);
    cudaFuncSetAttribute(finish_kernel,
                         cudaFuncAttributeMaxDynamicSharedMemorySize, finish_smem);

    span_chunk_kernel<<<dim3(B_, CCH), 192>>>(x, e1_span, e2_span, part);
    stage1_kernel    <<<dim3(B_ / TM1, KSPLIT), 256, stage1_smem>>>(
        part, x, e1_span, e2_span, W1, h1p);
    finish_kernel    <<<B_ / TMF, 256, finish_smem>>>(h1p, b1, W2, b2, W3, b3, out);
}

// round 15
// speedup vs baseline: 1.1767x; 1.0100x over previous
#include <cuda_runtime.h>
#include <math.h>

#define B_ 1024
#define S_ 512
#define D_ 768
#define FEAT 2304      // 3*D
#define H1 256
#define H2 64
#define NC 4

#define CCH 6          // union-chunks per batch in span phase

#define TM1 32         // batches per stage1 block
#define NPAIR (TM1/2)  // 16 packed f32 pairs
#define SFSTRIDE (NPAIR + 2)   // padded smem row stride (u64s), keeps 16B align
#define KSPLIT 9
#define KCHUNK 256     // FEAT / KSPLIT  (divides 768 -> chunk regions are pure)
#define KT 32          // W1 k-tile staged in smem
#define NKT (KCHUNK/KT)

#define TMF 2          // batches per finish block

// Scratch (static device globals; no allocation allowed)
__device__ float g_part[2 * CCH * B_ * D_];     // [e][c][b][f] raw span sums
__device__ float g_h1p[KSPLIT * B_ * H1];       // [chunk][b][j] stage1 partials

// ---------------------------------------------------------------------------
// packed fp32x2 helpers (FFMA2 path — PTX-only on sm_103a)
// ---------------------------------------------------------------------------
__device__ __forceinline__ unsigned long long pack2(float lo, float hi) {
    unsigned long long u;
    asm("mov.b64 %0, {%1, %2};" : "=l"(u) : "f"(lo), "f"(hi));
    return u;
}
__device__ __forceinline__ void unpack2(unsigned long long u, float& lo, float& hi) {
    asm("mov.b64 {%0, %1}, %2;" : "=f"(lo), "=f"(hi) : "l"(u));
}
__device__ __forceinline__ void ffma2(unsigned long long& d, unsigned long long a,
                                      unsigned long long b, unsigned long long c) {
    asm("fma.rn.f32x2 %0, %1, %2, %3;" : "=l"(d) : "l"(a), "l"(b), "l"(c));
}
__device__ __forceinline__ void cp_async16(void* smem_dst, const void* gsrc) {
    unsigned int s = (unsigned int)__cvta_generic_to_shared(smem_dst);
    asm volatile("cp.async.cg.shared.global [%0], [%1], 16;" :: "r"(s), "l"(gsrc));
}
#define CP_COMMIT()  asm volatile("cp.async.commit_group;" ::: "memory")
#define CP_WAIT1()   asm volatile("cp.async.wait_group 1;" ::: "memory")
#define CP_WAIT0()   asm volatile("cp.async.wait_group 0;" ::: "memory")

// ---------------------------------------------------------------------------
// Kernel 1: span partial sums over 1/CCH of the CONCATENATED UNION of spans.
// grid = (B, CCH), 192 threads; thread t owns float4 (cols 4t..4t+3).
// Streaming loads/stores: x and part have zero reuse.  (R11-proven, smem 0.)
// ---------------------------------------------------------------------------
__global__ __launch_bounds__(192) void span_chunk_kernel(
    const float* __restrict__ x,
    const int*   __restrict__ e1_span,
    const int*   __restrict__ e2_span,
    float*       __restrict__ part)
{
    const int b = blockIdx.x;
    const int c = blockIdx.y;
    const int t = threadIdx.x;

    int lo1 = e1_span[2 * b], hi1 = e1_span[2 * b + 1];
    if (hi1 < lo1 + 1) hi1 = lo1 + 1;
    int lo2 = e2_span[2 * b], hi2 = e2_span[2 * b + 1];
    if (hi2 < lo2 + 1) hi2 = lo2 + 1;

    const int u_lo = min(lo1, lo2);
    const int u_hi = max(hi1, hi2);
    int g_lo = min(hi1, hi2);
    int g_hi = max(lo1, lo2);
    if (g_hi < g_lo) { g_lo = u_hi; g_hi = u_hi; }   // overlap: no gap

    const int L1 = g_lo - u_lo;          // segment 1 length
    const int L2 = u_hi - g_hi;          // segment 2 length
    const int L  = L1 + L2;

    const int r0 = (c * L) / CCH;        // my slice of the concatenated union
    const int r1 = ((c + 1) * L) / CCH;

    const int s1a = u_lo + min(r0, L1);
    const int s1b = u_lo + min(r1, L1);
    const int s2a = g_hi + max(r0 - L1, 0);
    const int s2b = g_hi + max(r1 - L1, 0);

    const float4* xb = (const float4*)(x + (size_t)b * S_ * D_);

    float4 a1 = make_float4(0.f, 0.f, 0.f, 0.f);
    float4 a2 = make_float4(0.f, 0.f, 0.f, 0.f);

    #pragma unroll 1
    for (int seg = 0; seg < 2; seg++) {
        const int s0 = (seg == 0) ? s1a : s2a;
        const int s1 = (seg == 0) ? s1b : s2b;
        int s = s0;
        for (; s + 4 <= s1; s += 4) {
            float4 q0 = __ldcs(&xb[(size_t)(s + 0) * 192 + t]);
            float4 q1 = __ldcs(&xb[(size_t)(s + 1) * 192 + t]);
            float4 q2 = __ldcs(&xb[(size_t)(s + 2) * 192 + t]);
            float4 q3 = __ldcs(&xb[(size_t)(s + 3) * 192 + t]);
            #pragma unroll
            for (int u = 0; u < 4; u++) {
                const int ss = s + u;
                const float4 r = (u == 0) ? q0 : (u == 1) ? q1 : (u == 2) ? q2 : q3;
                const float p1 = (ss >= lo1 && ss < hi1) ? 1.0f : 0.0f;
                const float p2 = (ss >= lo2 && ss < hi2) ? 1.0f : 0.0f;
                a1.x = fmaf(r.x, p1, a1.x); a1.y = fmaf(r.y, p1, a1.y);
                a1.z = fmaf(r.z, p1, a1.z); a1.w = fmaf(r.w, p1, a1.w);
                a2.x = fmaf(r.x, p2, a2.x); a2.y = fmaf(r.y, p2, a2.y);
                a2.z = fmaf(r.z, p2, a2.z); a2.w = fmaf(r.w, p2, a2.w);
            }
        }
        for (; s < s1; s++) {
            float4 r = __ldcs(&xb[(size_t)s * 192 + t]);
            const float p1 = (s >= lo1 && s < hi1) ? 1.0f : 0.0f;
            const float p2 = (s >= lo2 && s < hi2) ? 1.0f : 0.0f;
            a1.x = fmaf(r.x, p1, a1.x); a1.y = fmaf(r.y, p1, a1.y);
            a1.z = fmaf(r.z, p1, a1.z); a1.w = fmaf(r.w, p1, a1.w);
            a2.x = fmaf(r.x, p2, a2.x); a2.y = fmaf(r.y, p2, a2.y);
            a2.z = fmaf(r.z, p2, a2.z); a2.w = fmaf(r.w, p2, a2.w);
        }
    }

    float4* p1 = (float4*)(part + ((size_t)(0 * CCH + c) * B_ + b) * D_);
    float4* p2 = (float4*)(part + ((size_t)(1 * CCH + c) * B_ + b) * D_);
    __stcs(&p1[t], a1);
    __stcs(&p2[t], a2);
}

// ---------------------------------------------------------------------------
// Kernel 2: stage-1 GEMM partials with packed f32x2 FMA + cp.async
// double-buffered W tiles (hardware-async global->smem a full tile ahead).
// grid = (B/TM1, KSPLIT) = 288 blocks, 256 threads, ~100.8KB smem (2/SM).
// ---------------------------------------------------------------------------
__global__ __launch_bounds__(256) void stage1_kernel(
    const float* __restrict__ part,
    const float* __restrict__ x,
    const int*   __restrict__ e1_span,
    const int*   __restrict__ e2_span,
    const float* __restrict__ W1,
    float*       __restrict__ h1p)
{
    extern __shared__ unsigned long long smem_dyn[];
    unsigned long long* sfP = smem_dyn;                        // KCHUNK*SFSTRIDE
    float* sW = (float*)(smem_dyn + KCHUNK * SFSTRIDE);        // 2 x KT*H1 floats

    const int j     = threadIdx.x;
    const int b0    = blockIdx.x * TM1;
    const int chunk = blockIdx.y;

    const float* W1c = W1 + (size_t)chunk * KCHUNK * H1;

    // kick off async copy of W tile 0 immediately (overlaps sfP staging)
    {
        const float4* src = (const float4*)W1c;
        float4*       dst = (float4*)sW;
        #pragma unroll
        for (int i = 0; i < (KT * H1 / 4) / 256; i++)
            cp_async16(dst + j + i * 256, src + j + i * 256);
        CP_COMMIT();
    }

    // staging: thread = (pair p = j>>4, kgroup kg = j&15); coalesced float4s.
    {
        const int kg = j & 15;
        const int p  = j >> 4;
        const int bA = b0 + 2 * p;
        const int bB = bA + 1;

        if (chunk >= 6) {
            // cls region: read x[b][0][k0+k]
            const int k0 = chunk * KCHUNK - 1536;
            const float* rA = x + (size_t)bA * S_ * D_ + k0;
            const float* rB = x + (size_t)bB * S_ * D_ + k0;
            #pragma unroll
            for (int kb = 0; kb < KCHUNK / 64; kb++) {
                const int k = kb * 64 + kg * 4;
                const float4 v0 = *(const float4*)(rA + k);
                const float4 v1 = *(const float4*)(rB + k);
                sfP[(k + 0) * SFSTRIDE + p] = pack2(v0.x, v1.x);
                sfP[(k + 1) * SFSTRIDE + p] = pack2(v0.y, v1.y);
                sfP[(k + 2) * SFSTRIDE + p] = pack2(v0.z, v1.z);
                sfP[(k + 3) * SFSTRIDE + p] = pack2(v0.w, v1.w);
            }
        } else {
            const int e  = (chunk < 3) ? 0 : 1;
            const int k0 = chunk * KCHUNK - e * 768;
            const int* sp = e ? e2_span : e1_span;
            int loA = sp[2 * bA], hiA = sp[2 * bA + 1];
            if (hiA < loA + 1) hiA = loA + 1;
            int loB = sp[2 * bB], hiB = sp[2 * bB + 1];
            if (hiB < loB + 1) hiB = loB + 1;
            const float invA = 1.0f / (float)(hiA - loA);
            const float invB = 1.0f / (float)(hiB - loB);

            const float* pA = part + ((size_t)(e * CCH) * B_ + bA) * D_ + k0;
            const float* pB = part + ((size_t)(e * CCH) * B_ + bB) * D_ + k0;
            const size_t cs = (size_t)B_ * D_;

            #pragma unroll
            for (int kb = 0; kb < KCHUNK / 64; kb++) {
                const int k = kb * 64 + kg * 4;
                float4 sA = make_float4(0.f, 0.f, 0.f, 0.f);
                float4 sB = make_float4(0.f, 0.f, 0.f, 0.f);
                #pragma unroll
                for (int cc = 0; cc < CCH; cc++) {
                    const float4 vA = *(const float4*)(pA + cc * cs + k);
                    const float4 vB = *(const float4*)(pB + cc * cs + k);
                    sA.x += vA.x; sA.y += vA.y; sA.z += vA.z; sA.w += vA.w;
                    sB.x += vB.x; sB.y += vB.y; sB.z += vB.z; sB.w += vB.w;
                }
                sfP[(k + 0) * SFSTRIDE + p] = pack2(sA.x * invA, sB.x * invB);
                sfP[(k + 1) * SFSTRIDE + p] = pack2(sA.y * invA, sB.y * invB);
                sfP[(k + 2) * SFSTRIDE + p] = pack2(sA.z * invA, sB.z * invB);
                sfP[(k + 3) * SFSTRIDE + p] = pack2(sA.w * invA, sB.w * invB);
            }
        }
    }

    const int jh = j & 127;          // column pair: jh, jh+128
    const int mg = j >> 7;           // batch-pair group: 8*mg .. 8*mg+7
    const int pb = 8 * mg;

    unsigned long long acc0[8], acc1[8];
    #pragma unroll
    for (int q = 0; q < 8; q++) { acc0[q] = 0ULL; acc1[q] = 0ULL; }

    __syncthreads();   // sfP ready

    #pragma unroll 1
    for (int t8 = 0; t8 < NKT; t8++) {
        if (t8 + 1 < NKT) {
            // async-prefetch NEXT tile into the other buffer
            const float4* src = (const float4*)(W1c + (size_t)(t8 + 1) * KT * H1);
            float4*       dst = (float4*)(sW + ((t8 + 1) & 1) * KT * H1);
            #pragma unroll
            for (int i = 0; i < (KT * H1 / 4) / 256; i++)
                cp_async16(dst + j + i * 256, src + j + i * 256);
            CP_COMMIT();
            CP_WAIT1();          // tile t8 complete (next one still in flight)
        } else {
            CP_WAIT0();          // last tile complete
        }
        __syncthreads();         // tile t8 visible to all

        const float* sWb = sW + (t8 & 1) * KT * H1;
        const int kt = t8 * KT;

        #pragma unroll
        for (int kk = 0; kk < KT; kk++) {
            const float w0 = sWb[kk * H1 + jh];
            const float w1 = sWb[kk * H1 + jh + 128];
            const unsigned long long wp0 = pack2(w0, w0);
            const unsigned long long wp1 = pack2(w1, w1);
            const ulonglong2* fr = (const ulonglong2*)&sfP[(kt + kk) * SFSTRIDE + pb];
            #pragma unroll
            for (int q2 = 0; q2 < 4; q2++) {
                ulonglong2 f = fr[q2];          // broadcast LDS.128 (2 pairs)
                ffma2(acc0[2 * q2 + 0], f.x, wp0, acc0[2 * q2 + 0]);
                ffma2(acc0[2 * q2 + 1], f.y, wp0, acc0[2 * q2 + 1]);
                ffma2(acc1[2 * q2 + 0], f.x, wp1, acc1[2 * q2 + 0]);
                ffma2(acc1[2 * q2 + 1], f.y, wp1, acc1[2 * q2 + 1]);
            }
        }
        __syncthreads();         // compute done before buffer reuse
    }

    float* dst = h1p + ((size_t)chunk * B_ + b0) * H1;
    #pragma unroll
    for (int q = 0; q < 8; q++) {
        const int p = pb + q;
        float lo, hi;
        unpack2(acc0[q], lo, hi);
        dst[(2 * p + 0) * H1 + jh] = lo;
        dst[(2 * p + 1) * H1 + jh] = hi;
        unpack2(acc1[q], lo, hi);
        dst[(2 * p + 0) * H1 + jh + 128] = lo;
        dst[(2 * p + 1) * H1 + jh + 128] = hi;
    }
}

// ---------------------------------------------------------------------------
// Kernel 3: finish. 256 threads, grid B/TMF (=512 blocks).
// W2 fully staged in dynamic smem; stage-2 k-loop split across both
// thread-halves (k in [0,128) / [128,256)), partials combined in smem.
// ---------------------------------------------------------------------------
__global__ __launch_bounds__(256) void finish_kernel(
    const float* __restrict__ h1p,
    const float* __restrict__ b1,
    const float* __restrict__ W2, const float* __restrict__ b2,
    const float* __restrict__ W3, const float* __restrict__ b3,
    float*       __restrict__ out)
{
    extern __shared__ float fsm[];
    float* sW2  = fsm;                    // H1*H2 = 64 KB
    float* sh1  = sW2 + H1 * H2;          // TMF*H1 = 512
    float* sh2p = sh1 + TMF * H1;         // 2 * TMF*H2 = 256

    const int j  = threadIdx.x;
    const int b0 = blockIdx.x * TMF;

    // stage ALL of W2 (issued first so these loads overlap the h1p loads)
    {
        const float4* src = (const float4*)W2;
        float4*       dst = (float4*)sW2;
        #pragma unroll
        for (int i = 0; i < (H1 * H2 / 4) / 256; i++)
            dst[j + i * 256] = src[j + i * 256];
    }

    // sum split-K partials + bias + relu
    {
        const float bias = b1[j];
        #pragma unroll
        for (int m = 0; m < TMF; m++) {
            const size_t off = (size_t)(b0 + m) * H1 + j;
            float v = bias;
            #pragma unroll
            for (int c = 0; c < KSPLIT; c++)
                v += h1p[(size_t)c * B_ * H1 + off];
            sh1[m * H1 + j] = fmaxf(v, 0.f);
        }
    }
    __syncthreads();

    // stage 2, split-k: half = j>>7 handles k in [half*128, half*128+128)
    {
        const int half = j >> 7;          // 0 or 1
        const int idx  = j & 127;         // (m, j2)
        const int m    = idx >> 6;
        const int j2   = idx & 63;
        const int kb   = half * 128;
        float a = 0.f;
        #pragma unroll 16
        for (int k = 0; k < 128; k++)
            a = fmaf(sh1[m * H1 + kb + k], sW2[(kb + k) * H2 + j2], a);
        sh2p[half * (TMF * H2) + idx] = a;
    }
    __syncthreads();
    if (j < TMF * H2)
        sh2p[j] = fmaxf(sh2p[j] + sh2p[TMF * H2 + j] + b2[j & 63], 0.f);
    __syncthreads();

    // stage 3 + softmax: one thread per batch
    if (j < TMF) {
        const int mm = j;
        float l0 = b3[0], l1 = b3[1], l2 = b3[2], l3 = b3[3];
        #pragma unroll 8
        for (int k = 0; k < H2; k++) {
            const float h = sh2p[mm * H2 + k];
            l0 = fmaf(h, W3[k * NC + 0], l0);
            l1 = fmaf(h, W3[k * NC + 1], l1);
            l2 = fmaf(h, W3[k * NC + 2], l2);
            l3 = fmaf(h, W3[k * NC + 3], l3);
        }
        const float mx = fmaxf(fmaxf(l0, l1), fmaxf(l2, l3));
        const float e0 = __expf(l0 - mx), e1v = __expf(l1 - mx);
        const float e2v = __expf(l2 - mx), e3v = __expf(l3 - mx);
        const float inv = 1.0f / (e0 + e1v + e2v + e3v);
        float* o = out + (size_t)(b0 + mm) * NC;
        o[0] = e0 * inv; o[1] = e1v * inv; o[2] = e2v * inv; o[3] = e3v * inv;
    }
}

// ---------------------------------------------------------------------------
extern "C" void kernel_launch(void* const* d_in, const int* in_sizes, int n_in,
                              void* d_out, int out_size)
{
    const float* x       = (const float*)d_in[0];
    const int*   e1_span = (const int*)  d_in[1];
    const int*   e2_span = (const int*)  d_in[2];
    const float* W1      = (const float*)d_in[3];
    const float* b1      = (const float*)d_in[4];
    const float* W2      = (const float*)d_in[5];
    const float* b2      = (const float*)d_in[6];
    const float* W3      = (const float*)d_in[7];
    const float* b3      = (const float*)d_in[8];
    float* out = (float*)d_out;

    float *part, *h1p;
    cudaGetSymbolAddress((void**)&part, g_part);
    cudaGetSymbolAddress((void**)&h1p,  g_h1p);

    const int stage1_smem = KCHUNK * SFSTRIDE * 8 + 2 * KT * H1 * 4;    // 102400
    const int finish_smem = (H1 * H2 + TMF * H1 + 2 * TMF * H2) * 4;    // 68608
    cudaFuncSetAttribute(stage1_kernel,
                         cudaFuncAttributeMaxDynamicSharedMemorySize, stage1_smem);
    cudaFuncSetAttribute(finish_kernel,
                         cudaFuncAttributeMaxDynamicSharedMemorySize, finish_smem);

    span_chunk_kernel<<<dim3(B_, CCH), 192>>>(x, e1_span, e2_span, part);
    stage1_kernel    <<<dim3(B_ / TM1, KSPLIT), 256, stage1_smem>>>(
        part, x, e1_span, e2_span, W1, h1p);
    finish_kernel    <<<B_ / TMF, 256, finish_smem>>>(h1p, b1, W2, b2, W3, b3, out);
}